// round 2
// baseline (speedup 1.0000x reference)
#include <cuda_runtime.h>
#include <cstdint>

#define NN 50000
#define EE 800000
#define EPP 200000
#define DIM 128

// ---------------- scratch (static device allocations; no cudaMalloc) -------
__device__ int   g_deg[NN];
__device__ int   g_rowptr[NN + 1];
__device__ int   g_cursor[NN];
__device__ int   g_csr_src[EE];
__device__ float g_agg[NN * DIM];
__device__ float g_h[NN * DIM];
__device__ float g_z[NN * DIM];
// packed weights: pairs (W[2k][j], W[2k+1][j]) -> [64][128] float2, two mats per layer
__device__ float2 g_W1p[2 * 64 * DIM];
__device__ float2 g_W2p[2 * 64 * DIM];

#define FMA2(acc, a, b) \
    asm("fma.rn.f32x2 %0, %1, %2, %0;" : "+l"(acc) : "l"(a), "l"(b))

// ---------------- CSR build ------------------------------------------------
__global__ void k_zero_deg() {
    int i = blockIdx.x * blockDim.x + threadIdx.x;
    if (i < NN) g_deg[i] = 0;
}

__global__ void k_count(const int* __restrict__ dst) {
    int e = blockIdx.x * blockDim.x + threadIdx.x;
    if (e < EE) {
        unsigned d = (unsigned)dst[e];
        if (d < NN) atomicAdd(&g_deg[d], 1);
    }
}

__global__ void k_scan() {
    __shared__ int warp_sums[32];
    __shared__ int s_carry;
    int tid = threadIdx.x;  // 1024 threads
    if (tid == 0) s_carry = 0;
    __syncthreads();
    for (int base = 0; base < NN; base += 1024) {
        int i = base + tid;
        int v = (i < NN) ? g_deg[i] : 0;
        int x = v;
        #pragma unroll
        for (int o = 1; o < 32; o <<= 1) {
            int y = __shfl_up_sync(0xffffffffu, x, o);
            if ((tid & 31) >= o) x += y;
        }
        if ((tid & 31) == 31) warp_sums[tid >> 5] = x;
        __syncthreads();
        if (tid < 32) {
            int w = warp_sums[tid];
            #pragma unroll
            for (int o = 1; o < 32; o <<= 1) {
                int y = __shfl_up_sync(0xffffffffu, w, o);
                if (tid >= o) w += y;
            }
            warp_sums[tid] = w;
        }
        __syncthreads();
        int incl = x + ((tid >= 32) ? warp_sums[(tid >> 5) - 1] : 0) + s_carry;
        if (i < NN) {
            g_rowptr[i + 1] = incl;
            g_cursor[i] = incl - v;  // exclusive prefix
        }
        __syncthreads();
        if (tid == 1023) s_carry = incl;
        __syncthreads();
    }
    if (tid == 0) g_rowptr[0] = 0;
}

__global__ void k_fill(const int* __restrict__ src,
                       const int* __restrict__ dst) {
    int e = blockIdx.x * blockDim.x + threadIdx.x;
    if (e < EE) {
        unsigned d = (unsigned)dst[e];
        unsigned s = (unsigned)src[e];
        if (d < NN && s < NN) {
            int p = atomicAdd(&g_cursor[d], 1);
            if ((unsigned)p < EE) g_csr_src[p] = (int)s;
        }
    }
}

// ---------------- weight prepack -------------------------------------------
__global__ void k_prepack(const float* __restrict__ W1l, const float* __restrict__ W1r,
                          const float* __restrict__ W2l, const float* __restrict__ W2r) {
    int idx = blockIdx.x * blockDim.x + threadIdx.x;  // 0..8191
    if (idx >= 64 * DIM) return;
    int kp = idx / DIM, j = idx % DIM;
    int a = (2 * kp) * DIM + j, b = (2 * kp + 1) * DIM + j;
    g_W1p[idx]              = make_float2(W1l[a], W1l[b]);
    g_W1p[64 * DIM + idx]   = make_float2(W1r[a], W1r[b]);
    g_W2p[idx]              = make_float2(W2l[a], W2l[b]);
    g_W2p[64 * DIM + idx]   = make_float2(W2r[a], W2r[b]);
}

// ---------------- mean aggregation (warp per node) --------------------------
__global__ void k_agg(const float* __restrict__ feat_in, int use_h) {
    const float* feat = use_h ? g_h : feat_in;
    int warp_id = (blockIdx.x * blockDim.x + threadIdx.x) >> 5;
    int lane = threadIdx.x & 31;
    if (warp_id >= NN) return;
    int n = warp_id;
    int start = g_rowptr[n], end = g_rowptr[n + 1];
    const float4* f4 = (const float4*)feat;
    float4 acc = make_float4(0.f, 0.f, 0.f, 0.f);
    for (int base = start; base < end; base += 32) {
        int m = min(32, end - base);
        int sid = (lane < m) ? g_csr_src[base + lane] : 0;
        for (int t = 0; t < m; ++t) {
            int s = __shfl_sync(0xffffffffu, sid, t);
            float4 v = f4[s * 32 + lane];
            acc.x += v.x; acc.y += v.y; acc.z += v.z; acc.w += v.w;
        }
    }
    int d = end - start;
    float inv = 1.0f / (float)max(d, 1);
    acc.x *= inv; acc.y *= inv; acc.z *= inv; acc.w *= inv;
    ((float4*)g_agg)[n * 32 + lane] = acc;
}

// ---------------- fused dual GEMM: out = agg@Wl + feat@Wr + b (opt relu) ----
// 128 threads, 32 nodes/block; thread j = output column j.
// Packed f32x2 accumulation over (even-k, odd-k); fold in epilogue.
__global__ void __launch_bounds__(128) k_gemm(const float* __restrict__ feat_in,
                                              const float* __restrict__ bias,
                                              int layer /*1 or 2*/) {
    __shared__ float sA[32 * DIM];
    __shared__ float sB[32 * DIM];
    const float* feat = (layer == 1) ? feat_in : g_h;
    float* out = (layer == 1) ? g_h : g_z;
    const unsigned long long* Wp =
        (layer == 1) ? (const unsigned long long*)g_W1p : (const unsigned long long*)g_W2p;
    int j = threadIdx.x;
    int node0 = blockIdx.x * 32;

    // load tiles (zero-pad out-of-range rows)
    const float4* A4 = (const float4*)g_agg;
    const float4* B4 = (const float4*)feat;
    float4 z4 = make_float4(0.f, 0.f, 0.f, 0.f);
    #pragma unroll
    for (int q = 0; q < 8; ++q) {
        int idx = q * 128 + j;          // 0..1023 float4 slots
        int row = idx >> 5, c4 = idx & 31;
        int gr = node0 + row;
        ((float4*)sA)[idx] = (gr < NN) ? A4[gr * 32 + c4] : z4;
        ((float4*)sB)[idx] = (gr < NN) ? B4[gr * 32 + c4] : z4;
    }
    __syncthreads();

    unsigned long long acc[32];
    #pragma unroll
    for (int i = 0; i < 32; ++i) acc[i] = 0ull;

    const unsigned long long* WpL = Wp;             // [64][128]
    const unsigned long long* WpR = Wp + 64 * DIM;  // [64][128]

    for (int k4 = 0; k4 < 32; ++k4) {               // k = 4*k4
        unsigned long long wl0 = WpL[(k4 * 2 + 0) * DIM + j];
        unsigned long long wl1 = WpL[(k4 * 2 + 1) * DIM + j];
        unsigned long long wr0 = WpR[(k4 * 2 + 0) * DIM + j];
        unsigned long long wr1 = WpR[(k4 * 2 + 1) * DIM + j];
        int k = k4 * 4;
        #pragma unroll
        for (int i = 0; i < 32; ++i) {
            ulonglong2 a = *(const ulonglong2*)&sA[i * DIM + k];
            ulonglong2 b = *(const ulonglong2*)&sB[i * DIM + k];
            FMA2(acc[i], a.x, wl0);
            FMA2(acc[i], a.y, wl1);
            FMA2(acc[i], b.x, wr0);
            FMA2(acc[i], b.y, wr1);
        }
    }

    float bj = bias[j];
    bool do_relu = (layer == 1);
    #pragma unroll
    for (int i = 0; i < 32; ++i) {
        int gr = node0 + i;
        if (gr < NN) {
            float2 p = *(float2*)&acc[i];
            float v = p.x + p.y + bj;
            if (do_relu) v = fmaxf(v, 0.f);
            out[gr * DIM + j] = v;
        }
    }
}

// ---------------- link prediction (warp per pred edge) ----------------------
__global__ void k_pred(const int* __restrict__ ps,
                       const int* __restrict__ pd,
                       float* __restrict__ out) {
    int warp_id = (blockIdx.x * blockDim.x + threadIdx.x) >> 5;
    int lane = threadIdx.x & 31;
    if (warp_id >= EPP) return;
    const float4* z4 = (const float4*)g_z;
    unsigned a = (unsigned)ps[warp_id], b = (unsigned)pd[warp_id];
    if (a >= NN) a = 0;
    if (b >= NN) b = 0;
    float4 u = z4[(size_t)a * 32 + lane];
    float4 v = z4[(size_t)b * 32 + lane];
    float d = u.x * v.x + u.y * v.y + u.z * v.z + u.w * v.w;
    #pragma unroll
    for (int o = 16; o > 0; o >>= 1) d += __shfl_xor_sync(0xffffffffu, d, o);
    if (lane == 0) out[warp_id] = d;
}

// ---------------- launch ----------------------------------------------------
extern "C" void kernel_launch(void* const* d_in, const int* in_sizes, int n_in,
                              void* d_out, int out_size) {
    const float* x   = (const float*)d_in[0];
    const float* W1l = (const float*)d_in[1];
    const float* b1  = (const float*)d_in[2];
    const float* W1r = (const float*)d_in[3];
    const float* W2l = (const float*)d_in[4];
    const float* b2  = (const float*)d_in[5];
    const float* W2r = (const float*)d_in[6];
    const int* edge_index = (const int*)d_in[7];  // (2,E) int32
    const int* pred_edges = (const int*)d_in[8];  // (2,EP) int32
    float* out = (float*)d_out;

    const int* src = edge_index;
    const int* dst = edge_index + EE;
    const int* ps = pred_edges;
    const int* pd = pred_edges + EPP;

    // CSR build
    k_zero_deg<<<(NN + 255) / 256, 256>>>();
    k_count<<<(EE + 255) / 256, 256>>>(dst);
    k_scan<<<1, 1024>>>();
    k_fill<<<(EE + 255) / 256, 256>>>(src, dst);
    k_prepack<<<(64 * DIM + 255) / 256, 256>>>(W1l, W1r, W2l, W2r);

    // layer 1
    k_agg<<<(NN * 32 + 255) / 256, 256>>>(x, 0);
    k_gemm<<<(NN + 31) / 32, 128>>>(x, b1, 1);
    // layer 2
    k_agg<<<(NN * 32 + 255) / 256, 256>>>(nullptr, 1);
    k_gemm<<<(NN + 31) / 32, 128>>>(nullptr, b2, 2);
    // link prediction
    k_pred<<<(EPP * 32 + 255) / 256, 256>>>(ps, pd, out);
}